// round 16
// baseline (speedup 1.0000x reference)
#include <cuda_runtime.h>
#include <cuda_bf16.h>

// NormSelfAttention B=4,H=16,N=2048,D=128 — mma.sync bf16x3 + cp.async.
// R16 = R13 base (best) + persistent phase2 (KV loaded once per CTA,
// single-wave grid) + phase1 split-sum fused via REDG atomics (mid resets
// the fp32 accumulator for graph replay).
//  Phase1: g_kv[d,e] += sum_n (elu(K)+1)*m [n,d] * (V*m)[n,e]  (split-K=4,
//          atomic across splits)
//  Mid:    g_kv -> pre-swizzled bf16 hi/lo tiles; g_kv reset to 0
//  Phase2: out[n,e] = sum_d (elu(Q)+1)[n,d]*KV[d,e]; fused RMS norm

#define SEQ    2048
#define NBH    64
#define SPLITS 4

__device__ float    g_kv[(size_t)NBH * 16384];   // 4 MB fp32 accumulator
__device__ unsigned g_kvh[(size_t)NBH * 8192];   // 2 MB swizzled bf16 hi
__device__ unsigned g_kvl[(size_t)NBH * 8192];   // 2 MB swizzled bf16 lo

typedef unsigned u32;
typedef unsigned long long u64;

static __device__ __forceinline__ u32 smem_u32(const void* p) {
    u32 a;
    asm("{ .reg .u64 t; cvta.to.shared.u64 t, %1; cvt.u32.u64 %0, t; }"
        : "=r"(a) : "l"(p));
    return a;
}
static __device__ __forceinline__ float actf(float x) {
    return x > 0.0f ? x + 1.0f : __expf(x);
}
// hi = {bf16(x1),bf16(x0)}, lo = packed bf16 residuals (residual exact in f32)
static __device__ __forceinline__ void hilo(float x0, float x1, u32& h, u32& l) {
    asm("cvt.rn.bf16x2.f32 %0, %1, %2;" : "=r"(h) : "f"(x1), "f"(x0));
    float f0 = __uint_as_float(h << 16);
    float f1 = __uint_as_float(h & 0xFFFF0000u);
    asm("cvt.rn.bf16x2.f32 %0, %1, %2;" : "=r"(l) : "f"(x1 - f1), "f"(x0 - f0));
}
// 256B-row tile (128 cols bf16), xor-swizzled 16B units. col in b16 elems.
static __device__ __forceinline__ int sw_addr(int row, int col) {
    return (row << 8) + ((((col >> 3) ^ (row & 7)) << 4)) + ((col & 7) << 1);
}
// 32B-row tile (16 cols bf16): unit ^= (row>>2)&1 -> ldmatrix 8-row groups
// land on 8 distinct 16B banks.
static __device__ __forceinline__ int sw16(int row, int col) {
    return (row << 5) + (((((col >> 3) & 1) ^ ((row >> 2) & 1)) << 4)) + ((col & 7) << 1);
}

#define CP_A16(dst, src) \
    asm volatile("cp.async.cg.shared.global [%0], [%1], 16;" \
        :: "r"((u32)(dst)), "l"(src) : "memory")
#define CP_COMMIT() asm volatile("cp.async.commit_group;" ::: "memory")
#define CP_WAIT(n)  asm volatile("cp.async.wait_group %0;" :: "n"(n) : "memory")

#define LDSM4(r0, r1, r2, r3, a)                                              \
    asm volatile("ldmatrix.sync.aligned.m8n8.x4.shared.b16 {%0,%1,%2,%3}, [%4];" \
        : "=r"(r0), "=r"(r1), "=r"(r2), "=r"(r3) : "r"(a))
#define LDSM4T(r0, r1, r2, r3, a)                                             \
    asm volatile("ldmatrix.sync.aligned.m8n8.x4.trans.shared.b16 {%0,%1,%2,%3}, [%4];" \
        : "=r"(r0), "=r"(r1), "=r"(r2), "=r"(r3) : "r"(a))

static __device__ __forceinline__ void mma16816(float* c, const u32* a, const u32* b) {
    asm volatile(
        "mma.sync.aligned.m16n8k16.row.col.f32.bf16.bf16.f32 "
        "{%0,%1,%2,%3}, {%4,%5,%6,%7}, {%8,%9}, {%0,%1,%2,%3};"
        : "+f"(c[0]), "+f"(c[1]), "+f"(c[2]), "+f"(c[3])
        : "r"(a[0]), "r"(a[1]), "r"(a[2]), "r"(a[3]), "r"(b[0]), "r"(b[1]));
}

// ---------------------------------------------------------------------------
// Phase 1 (identical to R13 except atomic epilogue).
// grid (4, 64) = 256 CTAs -> single wave at occ 2.
// 8 warps: 2 d x 4 e; warp tile 64d x 32e.  512 n per CTA, 16 chunks of 32.
// dyn smem: bf16 tiles KH 0 / KL 8K / VH 16K / VL 24K;
// raw cp.async stages at 32K: 2 x 33024B (K 16K | V 16K | mask 128B). 96.5KB
// ---------------------------------------------------------------------------
#define P1_STAGE(s) (32768 + (s) * 33024)
#define SMEM1 (32768 + 2 * 33024)

__global__ __launch_bounds__(256, 2)
void phase1(const float* __restrict__ K, const float* __restrict__ V,
            const float* __restrict__ mask) {
    extern __shared__ char sm1[];
    const u32 sb = smem_u32(sm1);
    const int tid = threadIdx.x, lane = tid & 31, wid = tid >> 5;
    const int split = blockIdx.x, bh = blockIdx.y, b = bh >> 4;
    const int d_base = (wid >> 2) * 64, e_base = (wid & 3) * 32;

    float acc[4][4][4];
#pragma unroll
    for (int i = 0; i < 4; i++)
#pragma unroll
        for (int j = 0; j < 4; j++)
#pragma unroll
            for (int q = 0; q < 4; q++) acc[i][j][q] = 0.f;

    const float4* K4 = (const float4*)K + (size_t)bh * (SEQ * 32) + (size_t)split * (512 * 32);
    const float4* V4 = (const float4*)V + (size_t)bh * (SEQ * 32) + (size_t)split * (512 * 32);
    const float4* M4 = (const float4*)(mask + b * SEQ + split * 512);

    const int a_row_l = ((lane >> 4) & 1) * 8 + (lane & 7);   // trans A
    const int a_col_l = ((lane >> 3) & 1) * 8;
    const int b_row_l = ((lane >> 3) & 1) * 8 + (lane & 7);   // trans B
    const int b_col_l = ((lane >> 4) & 1) * 8;

    auto issue = [&](int c) {
        int st = P1_STAGE(c & 1);
        const float4* ks = K4 + (size_t)c * 1024;
        const float4* vs = V4 + (size_t)c * 1024;
#pragma unroll
        for (int it = 0; it < 4; it++) {
            int flat = tid + it * 256;
            CP_A16(sb + st + flat * 16, ks + flat);
            CP_A16(sb + st + 16384 + flat * 16, vs + flat);
        }
        if (tid < 8) CP_A16(sb + st + 32768 + tid * 16, M4 + c * 8 + tid);
        CP_COMMIT();
    };

    issue(0); issue(1);

    for (int c = 0; c < 16; c++) {
        CP_WAIT(1);
        __syncthreads();
        {   // convert raw stage -> bf16 hi/lo swizzled tiles
            int st = P1_STAGE(c & 1);
            const float* mk = (const float*)(sm1 + st + 32768);
#pragma unroll
            for (int it = 0; it < 4; it++) {
                int flat = tid + it * 256;
                int row  = flat >> 5;      // n local 0..31
                int fd   = flat & 31;      // d/4
                float m  = mk[row];
                float4 kq = *(const float4*)(sm1 + st + row * 512 + fd * 16);
                float4 vq = *(const float4*)(sm1 + st + 16384 + row * 512 + fd * 16);
                u32 h0, l0, h1, l1;
                int off = sw_addr(row, fd * 4);
                hilo(actf(kq.x) * m, actf(kq.y) * m, h0, l0);
                hilo(actf(kq.z) * m, actf(kq.w) * m, h1, l1);
                *(u64*)(sm1 + off)         = (u64)h0 | ((u64)h1 << 32);
                *(u64*)(sm1 + 8192 + off)  = (u64)l0 | ((u64)l1 << 32);
                hilo(vq.x * m, vq.y * m, h0, l0);
                hilo(vq.z * m, vq.w * m, h1, l1);
                *(u64*)(sm1 + 16384 + off) = (u64)h0 | ((u64)h1 << 32);
                *(u64*)(sm1 + 24576 + off) = (u64)l0 | ((u64)l1 << 32);
            }
        }
        __syncthreads();                   // tiles ready; raw stage free
        if (c + 2 < 16) issue(c + 2); else CP_COMMIT();

#pragma unroll
        for (int ks = 0; ks < 2; ks++) {
            int n0 = ks * 16;
            u32 ah[4][4], al[4][4];
#pragma unroll
            for (int mt = 0; mt < 4; mt++) {
                u32 ad = sb + sw_addr(n0 + a_row_l, d_base + mt * 16 + a_col_l);
                LDSM4T(ah[mt][0], ah[mt][1], ah[mt][2], ah[mt][3], ad);
                LDSM4T(al[mt][0], al[mt][1], al[mt][2], al[mt][3], ad + 8192);
            }
            u32 bhf[4][2], blf[4][2];
#pragma unroll
            for (int h = 0; h < 2; h++) {
                u32 ad = sb + 16384 + sw_addr(n0 + b_row_l, e_base + h * 16 + b_col_l);
                u32 r0, r1, r2, r3;
                LDSM4T(r0, r1, r2, r3, ad);
                bhf[2 * h][0] = r0; bhf[2 * h][1] = r1;
                bhf[2 * h + 1][0] = r2; bhf[2 * h + 1][1] = r3;
                LDSM4T(r0, r1, r2, r3, ad + 8192);
                blf[2 * h][0] = r0; blf[2 * h][1] = r1;
                blf[2 * h + 1][0] = r2; blf[2 * h + 1][1] = r3;
            }
#pragma unroll
            for (int mt = 0; mt < 4; mt++)
#pragma unroll
                for (int nt = 0; nt < 4; nt++) {
                    mma16816(acc[mt][nt], ah[mt], bhf[nt]);
                    mma16816(acc[mt][nt], ah[mt], blf[nt]);
                    mma16816(acc[mt][nt], al[mt], bhf[nt]);
                }
        }
    }

    // Atomic split-sum into fp32 accumulator (REDG, no return needed)
    float* outp = g_kv + (size_t)bh * 16384;
#pragma unroll
    for (int mt = 0; mt < 4; mt++)
#pragma unroll
        for (int nt = 0; nt < 4; nt++) {
            int d1 = d_base + mt * 16 + (lane >> 2);
            int e  = e_base + nt * 8 + (lane & 3) * 2;
            atomicAdd(outp + d1 * 128 + e,           acc[mt][nt][0]);
            atomicAdd(outp + d1 * 128 + e + 1,       acc[mt][nt][1]);
            atomicAdd(outp + (d1 + 8) * 128 + e,     acc[mt][nt][2]);
            atomicAdd(outp + (d1 + 8) * 128 + e + 1, acc[mt][nt][3]);
        }
}

// ---------------------------------------------------------------------------
// Mid. grid 512, 256 thr. g_kv -> pre-swizzled bf16 hi/lo tiles; reset g_kv
// to zero so the next graph replay starts from a clean accumulator.
// ---------------------------------------------------------------------------
__global__ __launch_bounds__(256)
void midk() {
    const int tid = threadIdx.x;
#pragma unroll
    for (int i = 0; i < 4; i++) {
        int idx = blockIdx.x * 1024 + i * 256 + tid;   // float2 idx 0..524287
        int bh = idx >> 13;
        int p  = idx & 8191;
        int d = p >> 6, e = (p & 63) * 2;
        float* src = g_kv + (size_t)bh * 16384 + d * 128 + e;
        float2 v = *(float2*)src;
        u32 h, l; hilo(v.x, v.y, h, l);
        int o = sw_addr(d, e) >> 2;
        g_kvh[(size_t)bh * 8192 + o] = h;
        g_kvl[(size_t)bh * 8192 + o] = l;
        *(float2*)src = make_float2(0.f, 0.f);         // replay reset
    }
}

// ---------------------------------------------------------------------------
// Phase 2. grid (4, 64) = 256 CTAs = ONE wave at occ 2; each CTA processes
// 4 consecutive 128-row n-tiles of one bh, loading KV ONCE.
// 8 warps: 2 n x 4 e; warp tile 64n x 32e.  32 global Q chunks (8KB, 16 d).
// dyn smem (106.5+ KB): KVH 0 / KVL 32K / QRAW 64K (ring 3 x 8K,
//   thread-private) / QH 88K (2 x 4K) / QL 96K (2 x 4K) / RED 104K / SCL.
// Iteration t: MMA(t) -> wait(1) -> conv(t+1) -> issue(t+3) -> sync ->
//   (every 8th) RMS epilogue overlapped with next tile's in-flight loads.
// ---------------------------------------------------------------------------
#define P2_RAW 65536
#define P2_QH  90112
#define P2_QL  98304
#define P2_RED 106496
#define P2_SCL 108544
#define SMEM2  109056

__global__ __launch_bounds__(256, 2)
void phase2(const float* __restrict__ Q, float* __restrict__ O) {
    extern __shared__ char sm2[];
    const u32 sb = smem_u32(sm2);
    const int tid = threadIdx.x, lane = tid & 31, wid = tid >> 5;
    const int tgroup = blockIdx.x, bh = blockIdx.y;
    const int m_base = (wid >> 2) * 64, e_base = (wid & 3) * 32;

    const float4* gh = (const float4*)(g_kvh + (size_t)bh * 8192);
    const float4* gl = (const float4*)(g_kvl + (size_t)bh * 8192);
    // 512 rows of Q for this CTA (4 tiles x 128)
    const float4* Q4 = (const float4*)Q + ((size_t)bh * SEQ + (size_t)tgroup * 512) * 32;

    auto issue_q = [&](int t) {          // chunk t: tile t>>3, d-block t&7
#pragma unroll
        for (int it = 0; it < 2; it++) {
            int flat = tid + it * 256;
            int n = flat >> 2, fdl = flat & 3;
            CP_A16(sb + P2_RAW + (t % 3) * 8192 + n * 64 + fdl * 16,
                   Q4 + ((size_t)((t >> 3) * 128 + n)) * 32 + (t & 7) * 4 + fdl);
        }
        CP_COMMIT();
    };
    auto conv_q = [&](int t) {           // own-thread raw -> QH/QL buf (t&1)
#pragma unroll
        for (int it = 0; it < 2; it++) {
            int flat = tid + it * 256;
            int n = flat >> 2, fdl = flat & 3;
            float4 q = *(const float4*)(sm2 + P2_RAW + (t % 3) * 8192
                                        + n * 64 + fdl * 16);
            u32 h0, l0, h1, l1;
            hilo(actf(q.x), actf(q.y), h0, l0);
            hilo(actf(q.z), actf(q.w), h1, l1);
            int off = sw16(n, fdl * 4);
            *(u64*)(sm2 + P2_QH + (t & 1) * 4096 + off) = (u64)h0 | ((u64)h1 << 32);
            *(u64*)(sm2 + P2_QL + (t & 1) * 4096 + off) = (u64)l0 | ((u64)l1 << 32);
        }
    };

    // g0: KV tiles (cross-thread -> covered by the pre-loop sync)
#pragma unroll
    for (int it = 0; it < 8; it++) {
        int flat = tid + it * 256;
        CP_A16(sb + flat * 16, gh + flat);
        CP_A16(sb + 32768 + flat * 16, gl + flat);
    }
    CP_COMMIT();
    issue_q(0);   // g1
    issue_q(1);   // g2
    CP_WAIT(1);   // KV + q0 done
    conv_q(0);
    issue_q(2);   // g3
    __syncthreads();

    float acc[4][4][4];
#pragma unroll
    for (int i = 0; i < 4; i++)
#pragma unroll
        for (int j = 0; j < 4; j++)
#pragma unroll
            for (int q = 0; q < 4; q++) acc[i][j][q] = 0.f;

    const int a_row_l = ((lane >> 3) & 1) * 8 + (lane & 7);   // non-trans A
    const int a_col_l = ((lane >> 4) & 1) * 8;
    const int b_row_l = ((lane >> 3) & 1) * 8 + (lane & 7);   // trans B
    const int b_col_l = ((lane >> 4) & 1) * 8;

    float* RED = (float*)(sm2 + P2_RED);
    float* SCL = (float*)(sm2 + P2_SCL);

#pragma unroll 1
    for (int t = 0; t < 32; t++) {
        const int J = t & 7;
        // ---- MMA(t) on QH/QL buf[t&1] + KV rows J*16..J*16+15
        u32 bhf[4][2], blf[4][2];
#pragma unroll
        for (int h = 0; h < 2; h++) {
            u32 ad = sb + sw_addr(J * 16 + b_row_l, e_base + h * 16 + b_col_l);
            u32 r0, r1, r2, r3;
            LDSM4T(r0, r1, r2, r3, ad);
            bhf[2 * h][0] = r0; bhf[2 * h][1] = r1;
            bhf[2 * h + 1][0] = r2; bhf[2 * h + 1][1] = r3;
            LDSM4T(r0, r1, r2, r3, ad + 32768);
            blf[2 * h][0] = r0; blf[2 * h][1] = r1;
            blf[2 * h + 1][0] = r2; blf[2 * h + 1][1] = r3;
        }
#pragma unroll
        for (int mt = 0; mt < 4; mt++) {
            u32 ah[4], al[4];
            u32 ad = sb + P2_QH + (t & 1) * 4096
                   + sw16(m_base + mt * 16 + a_row_l, a_col_l);
            LDSM4(ah[0], ah[1], ah[2], ah[3], ad);
            LDSM4(al[0], al[1], al[2], al[3], ad + 8192);
#pragma unroll
            for (int nt = 0; nt < 4; nt++) {
                mma16816(acc[mt][nt], ah, bhf[nt]);
                mma16816(acc[mt][nt], ah, blf[nt]);
                mma16816(acc[mt][nt], al, bhf[nt]);
            }
        }
        // ---- stage next chunk (loads for it are already in flight)
        if (t < 31) {
            CP_WAIT(1);            // q(t+1) group retired (newest stays)
            conv_q(t + 1);
            if (t + 3 < 32) issue_q(t + 3); else CP_COMMIT();
        }
        __syncthreads();

        // ---- per-tile RMS epilogue (overlaps next tile's in-flight loads)
        if (J == 7) {
#pragma unroll
            for (int mt = 0; mt < 4; mt++) {
                float s0 = 0.f, s1 = 0.f;
#pragma unroll
                for (int nt = 0; nt < 4; nt++) {
                    s0 += acc[mt][nt][0] * acc[mt][nt][0] + acc[mt][nt][1] * acc[mt][nt][1];
                    s1 += acc[mt][nt][2] * acc[mt][nt][2] + acc[mt][nt][3] * acc[mt][nt][3];
                }
                s0 += __shfl_xor_sync(0xFFFFFFFFu, s0, 1);
                s0 += __shfl_xor_sync(0xFFFFFFFFu, s0, 2);
                s1 += __shfl_xor_sync(0xFFFFFFFFu, s1, 1);
                s1 += __shfl_xor_sync(0xFFFFFFFFu, s1, 2);
                if ((lane & 3) == 0) {
                    int r = m_base + mt * 16 + (lane >> 2);
                    RED[r * 4 + (wid & 3)]       = s0;
                    RED[(r + 8) * 4 + (wid & 3)] = s1;
                }
            }
            __syncthreads();
            if (tid < 128) {
                float s = RED[tid * 4] + RED[tid * 4 + 1]
                        + RED[tid * 4 + 2] + RED[tid * 4 + 3];
                SCL[tid] = rsqrtf(s * (1.0f / 128.0f) + 1e-6f);
            }
            __syncthreads();

            float* Ob = O + ((size_t)bh * SEQ + (size_t)tgroup * 512
                             + (size_t)(t >> 3) * 128) * 128;
#pragma unroll
            for (int mt = 0; mt < 4; mt++) {
                int r1 = m_base + mt * 16 + (lane >> 2);
                float sc1 = SCL[r1], sc2 = SCL[r1 + 8];
#pragma unroll
                for (int nt = 0; nt < 4; nt++) {
                    int e = e_base + nt * 8 + (lane & 3) * 2;
                    *(float2*)(Ob + (size_t)r1 * 128 + e) =
                        make_float2(acc[mt][nt][0] * sc1, acc[mt][nt][1] * sc1);
                    *(float2*)(Ob + (size_t)(r1 + 8) * 128 + e) =
                        make_float2(acc[mt][nt][2] * sc2, acc[mt][nt][3] * sc2);
                    acc[mt][nt][0] = 0.f; acc[mt][nt][1] = 0.f;
                    acc[mt][nt][2] = 0.f; acc[mt][nt][3] = 0.f;
                }
            }
            __syncthreads();   // RED/SCL free before next tile's epilogue
        }
    }
}

// ---------------------------------------------------------------------------
extern "C" void kernel_launch(void* const* d_in, const int* in_sizes, int n_in,
                              void* d_out, int out_size) {
    const float* Q    = (const float*)d_in[0];
    const float* K    = (const float*)d_in[1];
    const float* V    = (const float*)d_in[2];
    const float* mask = (const float*)d_in[3];
    float*       O    = (float*)d_out;

    cudaFuncSetAttribute(phase1, cudaFuncAttributeMaxDynamicSharedMemorySize, SMEM1);
    cudaFuncSetAttribute(phase2, cudaFuncAttributeMaxDynamicSharedMemorySize, SMEM2);

    phase1<<<dim3(SPLITS, NBH), 256, SMEM1>>>(K, V, mask);
    midk<<<512, 256>>>();
    phase2<<<dim3(4, NBH), 256, SMEM2>>>(Q, O);
}

// round 17
// speedup vs baseline: 1.1276x; 1.1276x over previous
#include <cuda_runtime.h>
#include <cuda_bf16.h>

// NormSelfAttention B=4,H=16,N=2048,D=128 — mma.sync bf16x3 + cp.async.
// R17 = R13 (best measured: 98.8us) + phase2 lookahead depth 3.
//  Phase1: KVpart[d,e] = sum_n (elu(K)+1)*m [n,d] * (V*m)[n,e]   split-K=4
//  Mid:    KV = sum splits -> pre-swizzled bf16 hi/lo tiles
//  Phase2: out[n,e] = sum_d (elu(Q)+1)[n,d]*KV[d,e]; fused RMS norm

#define SEQ    2048
#define NBH    64
#define SPLITS 4

__device__ float    g_kvpart[(size_t)NBH * SPLITS * 128 * 128];  // 16 MB
__device__ unsigned g_kvh[(size_t)NBH * 8192];                   // 2 MB
__device__ unsigned g_kvl[(size_t)NBH * 8192];                   // 2 MB

typedef unsigned u32;
typedef unsigned long long u64;

static __device__ __forceinline__ u32 smem_u32(const void* p) {
    u32 a;
    asm("{ .reg .u64 t; cvta.to.shared.u64 t, %1; cvt.u32.u64 %0, t; }"
        : "=r"(a) : "l"(p));
    return a;
}
static __device__ __forceinline__ float actf(float x) {
    return x > 0.0f ? x + 1.0f : __expf(x);
}
// hi = {bf16(x1),bf16(x0)}, lo = packed bf16 residuals (residual exact in f32)
static __device__ __forceinline__ void hilo(float x0, float x1, u32& h, u32& l) {
    asm("cvt.rn.bf16x2.f32 %0, %1, %2;" : "=r"(h) : "f"(x1), "f"(x0));
    float f0 = __uint_as_float(h << 16);
    float f1 = __uint_as_float(h & 0xFFFF0000u);
    asm("cvt.rn.bf16x2.f32 %0, %1, %2;" : "=r"(l) : "f"(x1 - f1), "f"(x0 - f0));
}
// 256B-row tile (128 cols bf16), xor-swizzled 16B units. col in b16 elems.
static __device__ __forceinline__ int sw_addr(int row, int col) {
    return (row << 8) + ((((col >> 3) ^ (row & 7)) << 4)) + ((col & 7) << 1);
}
// 32B-row tile (16 cols bf16): unit ^= (row>>2)&1 -> ldmatrix 8-row groups
// land on 8 distinct 16B banks.
static __device__ __forceinline__ int sw16(int row, int col) {
    return (row << 5) + (((((col >> 3) & 1) ^ ((row >> 2) & 1)) << 4)) + ((col & 7) << 1);
}

#define CP_A16(dst, src) \
    asm volatile("cp.async.cg.shared.global [%0], [%1], 16;" \
        :: "r"((u32)(dst)), "l"(src) : "memory")
#define CP_COMMIT() asm volatile("cp.async.commit_group;" ::: "memory")
#define CP_WAIT(n)  asm volatile("cp.async.wait_group %0;" :: "n"(n) : "memory")

#define LDSM4(r0, r1, r2, r3, a)                                              \
    asm volatile("ldmatrix.sync.aligned.m8n8.x4.shared.b16 {%0,%1,%2,%3}, [%4];" \
        : "=r"(r0), "=r"(r1), "=r"(r2), "=r"(r3) : "r"(a))
#define LDSM4T(r0, r1, r2, r3, a)                                             \
    asm volatile("ldmatrix.sync.aligned.m8n8.x4.trans.shared.b16 {%0,%1,%2,%3}, [%4];" \
        : "=r"(r0), "=r"(r1), "=r"(r2), "=r"(r3) : "r"(a))

static __device__ __forceinline__ void mma16816(float* c, const u32* a, const u32* b) {
    asm volatile(
        "mma.sync.aligned.m16n8k16.row.col.f32.bf16.bf16.f32 "
        "{%0,%1,%2,%3}, {%4,%5,%6,%7}, {%8,%9}, {%0,%1,%2,%3};"
        : "+f"(c[0]), "+f"(c[1]), "+f"(c[2]), "+f"(c[3])
        : "r"(a[0]), "r"(a[1]), "r"(a[2]), "r"(a[3]), "r"(b[0]), "r"(b[1]));
}

// ---------------------------------------------------------------------------
// Phase 1 (identical to R13). grid (4, 64) = 256 CTAs, single wave at occ 2.
// 8 warps: 2 d x 4 e; warp tile 64d x 32e.  512 n per CTA, 16 chunks of 32.
// dyn smem: bf16 tiles KH 0 / KL 8K / VH 16K / VL 24K;
// raw cp.async stages at 32K: 2 x 33024B (K 16K | V 16K | mask 128B). 96.5KB
// ---------------------------------------------------------------------------
#define P1_STAGE(s) (32768 + (s) * 33024)
#define SMEM1 (32768 + 2 * 33024)

__global__ __launch_bounds__(256, 2)
void phase1(const float* __restrict__ K, const float* __restrict__ V,
            const float* __restrict__ mask) {
    extern __shared__ char sm1[];
    const u32 sb = smem_u32(sm1);
    const int tid = threadIdx.x, lane = tid & 31, wid = tid >> 5;
    const int split = blockIdx.x, bh = blockIdx.y, b = bh >> 4;
    const int d_base = (wid >> 2) * 64, e_base = (wid & 3) * 32;

    float acc[4][4][4];
#pragma unroll
    for (int i = 0; i < 4; i++)
#pragma unroll
        for (int j = 0; j < 4; j++)
#pragma unroll
            for (int q = 0; q < 4; q++) acc[i][j][q] = 0.f;

    const float4* K4 = (const float4*)K + (size_t)bh * (SEQ * 32) + (size_t)split * (512 * 32);
    const float4* V4 = (const float4*)V + (size_t)bh * (SEQ * 32) + (size_t)split * (512 * 32);
    const float4* M4 = (const float4*)(mask + b * SEQ + split * 512);

    const int a_row_l = ((lane >> 4) & 1) * 8 + (lane & 7);   // trans A
    const int a_col_l = ((lane >> 3) & 1) * 8;
    const int b_row_l = ((lane >> 3) & 1) * 8 + (lane & 7);   // trans B
    const int b_col_l = ((lane >> 4) & 1) * 8;

    auto issue = [&](int c) {
        int st = P1_STAGE(c & 1);
        const float4* ks = K4 + (size_t)c * 1024;
        const float4* vs = V4 + (size_t)c * 1024;
#pragma unroll
        for (int it = 0; it < 4; it++) {
            int flat = tid + it * 256;
            CP_A16(sb + st + flat * 16, ks + flat);
            CP_A16(sb + st + 16384 + flat * 16, vs + flat);
        }
        if (tid < 8) CP_A16(sb + st + 32768 + tid * 16, M4 + c * 8 + tid);
        CP_COMMIT();
    };

    issue(0); issue(1);

    for (int c = 0; c < 16; c++) {
        CP_WAIT(1);
        __syncthreads();
        {   // convert raw stage -> bf16 hi/lo swizzled tiles
            int st = P1_STAGE(c & 1);
            const float* mk = (const float*)(sm1 + st + 32768);
#pragma unroll
            for (int it = 0; it < 4; it++) {
                int flat = tid + it * 256;
                int row  = flat >> 5;      // n local 0..31
                int fd   = flat & 31;      // d/4
                float m  = mk[row];
                float4 kq = *(const float4*)(sm1 + st + row * 512 + fd * 16);
                float4 vq = *(const float4*)(sm1 + st + 16384 + row * 512 + fd * 16);
                u32 h0, l0, h1, l1;
                int off = sw_addr(row, fd * 4);
                hilo(actf(kq.x) * m, actf(kq.y) * m, h0, l0);
                hilo(actf(kq.z) * m, actf(kq.w) * m, h1, l1);
                *(u64*)(sm1 + off)         = (u64)h0 | ((u64)h1 << 32);
                *(u64*)(sm1 + 8192 + off)  = (u64)l0 | ((u64)l1 << 32);
                hilo(vq.x * m, vq.y * m, h0, l0);
                hilo(vq.z * m, vq.w * m, h1, l1);
                *(u64*)(sm1 + 16384 + off) = (u64)h0 | ((u64)h1 << 32);
                *(u64*)(sm1 + 24576 + off) = (u64)l0 | ((u64)l1 << 32);
            }
        }
        __syncthreads();                   // tiles ready; raw stage free
        if (c + 2 < 16) issue(c + 2); else CP_COMMIT();

#pragma unroll
        for (int ks = 0; ks < 2; ks++) {
            int n0 = ks * 16;
            u32 ah[4][4], al[4][4];
#pragma unroll
            for (int mt = 0; mt < 4; mt++) {
                u32 ad = sb + sw_addr(n0 + a_row_l, d_base + mt * 16 + a_col_l);
                LDSM4T(ah[mt][0], ah[mt][1], ah[mt][2], ah[mt][3], ad);
                LDSM4T(al[mt][0], al[mt][1], al[mt][2], al[mt][3], ad + 8192);
            }
            u32 bhf[4][2], blf[4][2];
#pragma unroll
            for (int h = 0; h < 2; h++) {
                u32 ad = sb + 16384 + sw_addr(n0 + b_row_l, e_base + h * 16 + b_col_l);
                u32 r0, r1, r2, r3;
                LDSM4T(r0, r1, r2, r3, ad);
                bhf[2 * h][0] = r0; bhf[2 * h][1] = r1;
                bhf[2 * h + 1][0] = r2; bhf[2 * h + 1][1] = r3;
                LDSM4T(r0, r1, r2, r3, ad + 8192);
                blf[2 * h][0] = r0; blf[2 * h][1] = r1;
                blf[2 * h + 1][0] = r2; blf[2 * h + 1][1] = r3;
            }
#pragma unroll
            for (int mt = 0; mt < 4; mt++)
#pragma unroll
                for (int nt = 0; nt < 4; nt++) {
                    mma16816(acc[mt][nt], ah[mt], bhf[nt]);
                    mma16816(acc[mt][nt], ah[mt], blf[nt]);
                    mma16816(acc[mt][nt], al[mt], bhf[nt]);
                }
        }
    }

    float* outp = g_kvpart + ((size_t)(bh * SPLITS + split)) * 16384;
#pragma unroll
    for (int mt = 0; mt < 4; mt++)
#pragma unroll
        for (int nt = 0; nt < 4; nt++) {
            int d1 = d_base + mt * 16 + (lane >> 2);
            int e  = e_base + nt * 8 + (lane & 3) * 2;
            *(float2*)(outp + d1 * 128 + e) =
                make_float2(acc[mt][nt][0], acc[mt][nt][1]);
            *(float2*)(outp + (d1 + 8) * 128 + e) =
                make_float2(acc[mt][nt][2], acc[mt][nt][3]);
        }
}

// ---------------------------------------------------------------------------
// Mid (identical to R13). grid 512, 256 thr. Sum 4 splits, emit swizzled
// bf16 hi/lo tiles.
// ---------------------------------------------------------------------------
__global__ __launch_bounds__(256)
void midk() {
    const int tid = threadIdx.x;
#pragma unroll
    for (int i = 0; i < 4; i++) {
        int idx = blockIdx.x * 1024 + i * 256 + tid;   // 0..524287
        int bh = idx >> 13;
        int p  = idx & 8191;
        int d = p >> 6, e = (p & 63) * 2;
        const float* src = g_kvpart + (size_t)bh * (SPLITS * 16384);
        float sx = 0.f, sy = 0.f;
#pragma unroll
        for (int s = 0; s < SPLITS; s++) {
            float2 v = *(const float2*)(src + s * 16384 + d * 128 + e);
            sx += v.x; sy += v.y;
        }
        u32 h, l; hilo(sx, sy, h, l);
        int o = sw_addr(d, e) >> 2;
        g_kvh[(size_t)bh * 8192 + o] = h;
        g_kvl[(size_t)bh * 8192 + o] = l;
    }
}

// ---------------------------------------------------------------------------
// Phase 2 (R13 + lookahead 3). grid (16, 64) = 1024 CTAs, 128-row n-tiles,
// occ 2.  8 warps: 2 n x 4 e; warp tile 64n x 32e.  K in 8 chunks of 16 d.
// dyn smem (~99 KB): KVH 0 / KVL 32K / QRAW 64K (ring 3 x 8K, thread-
// private) / QH 88K (2 x 4K) / QL 96K (2 x 4K) / RED / SCL.
// Iteration: MMA(J) -> wait(2) -> conv(J+1) -> issue(J+4) -> sync.
// 3 chunks (24KB) in flight per CTA.
// ---------------------------------------------------------------------------
#define P2_RAW 65536
#define P2_QH  90112
#define P2_QL  98304
#define P2_RED 106496
#define P2_SCL 108544
#define SMEM2  109056

__global__ __launch_bounds__(256, 2)
void phase2(const float* __restrict__ Q, float* __restrict__ O) {
    extern __shared__ char sm2[];
    const u32 sb = smem_u32(sm2);
    const int tid = threadIdx.x, lane = tid & 31, wid = tid >> 5;
    const int ntile = blockIdx.x, bh = blockIdx.y;
    const int m_base = (wid >> 2) * 64, e_base = (wid & 3) * 32;

    const float4* gh = (const float4*)(g_kvh + (size_t)bh * 8192);
    const float4* gl = (const float4*)(g_kvl + (size_t)bh * 8192);
    const float4* Q4 = (const float4*)Q + ((size_t)bh * SEQ + (size_t)ntile * 128) * 32;

    auto issue_q = [&](int j) {          // raw slot j%3, thread-private
#pragma unroll
        for (int it = 0; it < 2; it++) {
            int flat = tid + it * 256;
            int n = flat >> 2, fdl = flat & 3;
            CP_A16(sb + P2_RAW + (j % 3) * 8192 + n * 64 + fdl * 16,
                   Q4 + n * 32 + j * 4 + fdl);
        }
        CP_COMMIT();
    };
    auto conv_q = [&](int j) {           // own-thread raw -> QH/QL buf (j&1)
#pragma unroll
        for (int it = 0; it < 2; it++) {
            int flat = tid + it * 256;
            int n = flat >> 2, fdl = flat & 3;
            float4 q = *(const float4*)(sm2 + P2_RAW + (j % 3) * 8192
                                        + n * 64 + fdl * 16);
            u32 h0, l0, h1, l1;
            hilo(actf(q.x), actf(q.y), h0, l0);
            hilo(actf(q.z), actf(q.w), h1, l1);
            int off = sw16(n, fdl * 4);
            *(u64*)(sm2 + P2_QH + (j & 1) * 4096 + off) = (u64)h0 | ((u64)h1 << 32);
            *(u64*)(sm2 + P2_QL + (j & 1) * 4096 + off) = (u64)l0 | ((u64)l1 << 32);
        }
    };

    // g0: KV tiles (cross-thread -> covered by the pre-loop sync)
#pragma unroll
    for (int it = 0; it < 8; it++) {
        int flat = tid + it * 256;
        CP_A16(sb + flat * 16, gh + flat);
        CP_A16(sb + 32768 + flat * 16, gl + flat);
    }
    CP_COMMIT();
    issue_q(0);   // g1 = q0
    issue_q(1);   // g2 = q1
    issue_q(2);   // g3 = q2
    CP_WAIT(2);   // retire g0 (KV) + g1 (q0); q1,q2 stay in flight
    conv_q(0);
    issue_q(3);   // g4 = q3 (slot 0, just converted by this thread)
    __syncthreads();

    float acc[4][4][4];
#pragma unroll
    for (int i = 0; i < 4; i++)
#pragma unroll
        for (int j = 0; j < 4; j++)
#pragma unroll
            for (int q = 0; q < 4; q++) acc[i][j][q] = 0.f;

    const int a_row_l = ((lane >> 3) & 1) * 8 + (lane & 7);   // non-trans A
    const int a_col_l = ((lane >> 4) & 1) * 8;
    const int b_row_l = ((lane >> 3) & 1) * 8 + (lane & 7);   // trans B
    const int b_col_l = ((lane >> 4) & 1) * 8;

#pragma unroll
    for (int J = 0; J < 8; J++) {
        // ---- MMA(J) on QH/QL buf[J&1] + KV rows J*16..J*16+15
        u32 bhf[4][2], blf[4][2];
#pragma unroll
        for (int h = 0; h < 2; h++) {
            u32 ad = sb + sw_addr(J * 16 + b_row_l, e_base + h * 16 + b_col_l);
            u32 r0, r1, r2, r3;
            LDSM4T(r0, r1, r2, r3, ad);
            bhf[2 * h][0] = r0; bhf[2 * h][1] = r1;
            bhf[2 * h + 1][0] = r2; bhf[2 * h + 1][1] = r3;
            LDSM4T(r0, r1, r2, r3, ad + 32768);
            blf[2 * h][0] = r0; blf[2 * h][1] = r1;
            blf[2 * h + 1][0] = r2; blf[2 * h + 1][1] = r3;
        }
#pragma unroll
        for (int mt = 0; mt < 4; mt++) {
            u32 ah[4], al[4];
            u32 ad = sb + P2_QH + (J & 1) * 4096
                   + sw16(m_base + mt * 16 + a_row_l, a_col_l);
            LDSM4(ah[0], ah[1], ah[2], ah[3], ad);
            LDSM4(al[0], al[1], al[2], al[3], ad + 8192);
#pragma unroll
            for (int nt = 0; nt < 4; nt++) {
                mma16816(acc[mt][nt], ah, bhf[nt]);
                mma16816(acc[mt][nt], ah, blf[nt]);
                mma16816(acc[mt][nt], al, bhf[nt]);
            }
        }
        // ---- stage next chunk (3 chunks in flight)
        if (J < 7) {
            CP_WAIT(2);            // retire q(J+1); 2 newest stay in flight
            conv_q(J + 1);
            if (J + 4 < 8) issue_q(J + 4); else CP_COMMIT();
        }
        __syncthreads();
    }

    // RMS: quad shfl-reduce -> RED[128][4] -> scale -> direct scaled stores
    float* RED = (float*)(sm2 + P2_RED);
#pragma unroll
    for (int mt = 0; mt < 4; mt++) {
        float s0 = 0.f, s1 = 0.f;
#pragma unroll
        for (int nt = 0; nt < 4; nt++) {
            s0 += acc[mt][nt][0] * acc[mt][nt][0] + acc[mt][nt][1] * acc[mt][nt][1];
            s1 += acc[mt][nt][2] * acc[mt][nt][2] + acc[mt][nt][3] * acc[mt][nt][3];
        }
        s0 += __shfl_xor_sync(0xFFFFFFFFu, s0, 1);
        s0 += __shfl_xor_sync(0xFFFFFFFFu, s0, 2);
        s1 += __shfl_xor_sync(0xFFFFFFFFu, s1, 1);
        s1 += __shfl_xor_sync(0xFFFFFFFFu, s1, 2);
        if ((lane & 3) == 0) {
            int r = m_base + mt * 16 + (lane >> 2);
            RED[r * 4 + (wid & 3)]       = s0;
            RED[(r + 8) * 4 + (wid & 3)] = s1;
        }
    }
    __syncthreads();
    float* SCL = (float*)(sm2 + P2_SCL);
    if (tid < 128) {
        float s = RED[tid * 4] + RED[tid * 4 + 1] + RED[tid * 4 + 2] + RED[tid * 4 + 3];
        SCL[tid] = rsqrtf(s * (1.0f / 128.0f) + 1e-6f);
    }
    __syncthreads();

    float* Ob = O + ((size_t)bh * SEQ + (size_t)ntile * 128) * 128;
#pragma unroll
    for (int mt = 0; mt < 4; mt++) {
        int r1 = m_base + mt * 16 + (lane >> 2);
        float sc1 = SCL[r1], sc2 = SCL[r1 + 8];
#pragma unroll
        for (int nt = 0; nt < 4; nt++) {
            int e = e_base + nt * 8 + (lane & 3) * 2;
            *(float2*)(Ob + (size_t)r1 * 128 + e) =
                make_float2(acc[mt][nt][0] * sc1, acc[mt][nt][1] * sc1);
            *(float2*)(Ob + (size_t)(r1 + 8) * 128 + e) =
                make_float2(acc[mt][nt][2] * sc2, acc[mt][nt][3] * sc2);
        }
    }
}

// ---------------------------------------------------------------------------
extern "C" void kernel_launch(void* const* d_in, const int* in_sizes, int n_in,
                              void* d_out, int out_size) {
    const float* Q    = (const float*)d_in[0];
    const float* K    = (const float*)d_in[1];
    const float* V    = (const float*)d_in[2];
    const float* mask = (const float*)d_in[3];
    float*       O    = (float*)d_out;

    cudaFuncSetAttribute(phase1, cudaFuncAttributeMaxDynamicSharedMemorySize, SMEM1);
    cudaFuncSetAttribute(phase2, cudaFuncAttributeMaxDynamicSharedMemorySize, SMEM2);

    phase1<<<dim3(SPLITS, NBH), 256, SMEM1>>>(K, V, mask);
    midk<<<512, 256>>>();
    phase2<<<dim3(16, NBH), 256, SMEM2>>>(Q, O);
}